// round 1
// baseline (speedup 1.0000x reference)
#include <cuda_runtime.h>
#include <math.h>

#define Dm 1024
#define Hm 4096
#define Lm 12
#define Vm 50277

// ---------------- scratch (allocation-free: __device__ globals) ----------------
__device__ float g_x[Dm];                    // residual stream
__device__ float g_xk[Dm], g_xv[Dm], g_xr[Dm];
__device__ float g_k[Dm],  g_v[Dm],  g_r[Dm];
__device__ float g_rwkv[Dm];
__device__ float g_fxk[Dm], g_fxr[Dm];
__device__ float g_fk[Hm],  g_fr[Dm];
__device__ float g_xn[Dm];                   // final-LN output

// ---------------- reductions ----------------
__device__ __forceinline__ float warp_sum(float v) {
#pragma unroll
    for (int o = 16; o; o >>= 1) v += __shfl_down_sync(0xffffffffu, v, o);
    return v;
}

// blockDim.x == 1024 (32 warps)
__device__ float block_sum(float v, float* sbuf) {
    int lane = threadIdx.x & 31, wid = threadIdx.x >> 5;
    v = warp_sum(v);
    __syncthreads();
    if (lane == 0) sbuf[wid] = v;
    __syncthreads();
    if (wid == 0) {
        float t = sbuf[lane];
        t = warp_sum(t);
        if (lane == 0) sbuf[0] = t;
    }
    __syncthreads();
    return sbuf[0];
}

// ---------------- kernels ----------------

// x = LN(emb[token], ln0)
__global__ void k_embed(const int* __restrict__ tok, const float* __restrict__ emb,
                        const float* __restrict__ w, const float* __restrict__ b) {
    __shared__ float sbuf[32];
    int i = threadIdx.x;
    float xv = emb[(size_t)(*tok) * Dm + i];
    float mu = block_sum(xv, sbuf) * (1.0f / Dm);
    float d  = xv - mu;
    float var = block_sum(d * d, sbuf) * (1.0f / Dm);
    g_x[i] = d * rsqrtf(var + 1e-5f) * w[i] + b[i];
}

// xx = LN(x, ln1); xk/xv/xr mixes; state_out row1 = xx
__global__ void k_att_pre(const float* __restrict__ w, const float* __restrict__ b,
                          const float* __restrict__ tmk, const float* __restrict__ tmv,
                          const float* __restrict__ tmr,
                          const float* __restrict__ s_sa, float* __restrict__ xx_out) {
    __shared__ float sbuf[32];
    int i = threadIdx.x;
    float xv = g_x[i];
    float mu = block_sum(xv, sbuf) * (1.0f / Dm);
    float d  = xv - mu;
    float var = block_sum(d * d, sbuf) * (1.0f / Dm);
    float xx = d * rsqrtf(var + 1e-5f) * w[i] + b[i];
    float ss = s_sa[i];
    float mk = tmk[i], mv = tmv[i], mr = tmr[i];
    g_xk[i] = xx * mk + ss * (1.0f - mk);
    g_xv[i] = xx * mv + ss * (1.0f - mv);
    g_xr[i] = xx * mr + ss * (1.0f - mr);
    xx_out[i] = xx;
}

// k = kw@xk ; v = vw@xv ; r = sigmoid(rw@xr). warp-per-row. grid=384x256
__global__ void k_mv_kvr(const float* __restrict__ kw, const float* __restrict__ vw,
                         const float* __restrict__ rw) {
    __shared__ float sx[Dm];
    int mat = blockIdx.x >> 7;                 // 0..2 (128 blocks each)
    const float* W  = (mat == 0) ? kw : (mat == 1) ? vw : rw;
    const float* xv = (mat == 0) ? g_xk : (mat == 1) ? g_xv : g_xr;
    for (int j = threadIdx.x; j < Dm; j += 256) sx[j] = xv[j];
    __syncthreads();
    int warp = threadIdx.x >> 5, lane = threadIdx.x & 31;
    int row = ((blockIdx.x & 127) << 3) + warp;
    const float4* wr = (const float4*)(W + (size_t)row * Dm);
    const float4* xr4 = (const float4*)sx;
    float acc = 0.f;
#pragma unroll
    for (int j = 0; j < 8; j++) {
        float4 a = wr[j * 32 + lane];
        float4 c = xr4[j * 32 + lane];
        acc += a.x * c.x + a.y * c.y + a.z * c.z + a.w * c.w;
    }
    acc = warp_sum(acc);
    if (lane == 0) {
        if (mat == 0)      g_k[row] = acc;
        else if (mat == 1) g_v[row] = acc;
        else               g_r[row] = 1.0f / (1.0f + expf(-acc));
    }
}

// WKV recurrence + state update + rwkv = r * wkv
__global__ void k_wkv(const float* __restrict__ tf, const float* __restrict__ td,
                      const float* __restrict__ aa_in, const float* __restrict__ bb_in,
                      const float* __restrict__ pp_in,
                      float* __restrict__ aa_out, float* __restrict__ bb_out,
                      float* __restrict__ pp_out) {
    int i = threadIdx.x;
    float k = g_k[i], v = g_v[i];
    float aa = aa_in[i], bb = bb_in[i], pp = pp_in[i];
    float ww = tf[i] + k;
    float p  = fmaxf(pp, ww);
    float e1 = expf(pp - p), e2 = expf(ww - p);
    float wkv = (e1 * aa + e2 * v) / (e1 * bb + e2);
    float ww2 = pp + td[i];
    float p2  = fmaxf(ww2, k);
    float f1 = expf(ww2 - p2), f2 = expf(k - p2);
    aa_out[i] = f1 * aa + f2 * v;
    bb_out[i] = f1 * bb + f2;
    pp_out[i] = p2;
    g_rwkv[i] = g_r[i] * wkv;
}

// x += ow @ rwkv. grid=128x256
__global__ void k_mv_ow(const float* __restrict__ ow) {
    __shared__ float sx[Dm];
    for (int j = threadIdx.x; j < Dm; j += 256) sx[j] = g_rwkv[j];
    __syncthreads();
    int warp = threadIdx.x >> 5, lane = threadIdx.x & 31;
    int row = (blockIdx.x << 3) + warp;
    const float4* wr = (const float4*)(ow + (size_t)row * Dm);
    const float4* xr4 = (const float4*)sx;
    float acc = 0.f;
#pragma unroll
    for (int j = 0; j < 8; j++) {
        float4 a = wr[j * 32 + lane];
        float4 c = xr4[j * 32 + lane];
        acc += a.x * c.x + a.y * c.y + a.z * c.z + a.w * c.w;
    }
    acc = warp_sum(acc);
    if (lane == 0) g_x[row] += acc;
}

// yy = LN(x, ln2); fxk/fxr mixes; state_out row0 = yy
__global__ void k_ffn_pre(const float* __restrict__ w, const float* __restrict__ b,
                          const float* __restrict__ fmk, const float* __restrict__ fmr,
                          const float* __restrict__ s_ff, float* __restrict__ yy_out) {
    __shared__ float sbuf[32];
    int i = threadIdx.x;
    float xv = g_x[i];
    float mu = block_sum(xv, sbuf) * (1.0f / Dm);
    float d  = xv - mu;
    float var = block_sum(d * d, sbuf) * (1.0f / Dm);
    float yy = d * rsqrtf(var + 1e-5f) * w[i] + b[i];
    float sf = s_ff[i];
    float mk = fmk[i], mr = fmr[i];
    g_fxk[i] = yy * mk + sf * (1.0f - mk);
    g_fxr[i] = yy * mr + sf * (1.0f - mr);
    yy_out[i] = yy;
}

// rows 0..4095: fk = relu(fkw@fxk)^2 ; rows 4096..5119: fr = sigmoid(frw@fxr). grid=640x256
__global__ void k_mv_fkr(const float* __restrict__ fkw, const float* __restrict__ frw) {
    __shared__ float sx[Dm];
    int grow0 = blockIdx.x << 3;
    bool is_k = (grow0 < Hm);
    const float* xv = is_k ? g_fxk : g_fxr;
    for (int j = threadIdx.x; j < Dm; j += 256) sx[j] = xv[j];
    __syncthreads();
    int warp = threadIdx.x >> 5, lane = threadIdx.x & 31;
    int grow = grow0 + warp;
    const float* W;
    int row;
    if (is_k) { W = fkw; row = grow; }
    else      { W = frw; row = grow - Hm; }
    const float4* wr = (const float4*)(W + (size_t)row * Dm);
    const float4* xr4 = (const float4*)sx;
    float acc = 0.f;
#pragma unroll
    for (int j = 0; j < 8; j++) {
        float4 a = wr[j * 32 + lane];
        float4 c = xr4[j * 32 + lane];
        acc += a.x * c.x + a.y * c.y + a.z * c.z + a.w * c.w;
    }
    acc = warp_sum(acc);
    if (lane == 0) {
        if (is_k) { float t = fmaxf(acc, 0.0f); g_fk[row] = t * t; }
        else      { g_fr[row] = 1.0f / (1.0f + expf(-acc)); }
    }
}

// x += fr * (fvw @ fk). K=4096. grid=128x256, 16KB smem
__global__ void k_mv_fv(const float* __restrict__ fvw) {
    __shared__ float sfk[Hm];
    for (int j = threadIdx.x; j < Hm; j += 256) sfk[j] = g_fk[j];
    __syncthreads();
    int warp = threadIdx.x >> 5, lane = threadIdx.x & 31;
    int row = (blockIdx.x << 3) + warp;
    const float4* wr = (const float4*)(fvw + (size_t)row * Hm);
    const float4* xr4 = (const float4*)sfk;
    float acc = 0.f;
#pragma unroll
    for (int j = 0; j < 32; j++) {
        float4 a = wr[j * 32 + lane];
        float4 c = xr4[j * 32 + lane];
        acc += a.x * c.x + a.y * c.y + a.z * c.z + a.w * c.w;
    }
    acc = warp_sum(acc);
    if (lane == 0) g_x[row] += g_fr[row] * acc;
}

// xn = LN(x, lnout)
__global__ void k_final_ln(const float* __restrict__ w, const float* __restrict__ b) {
    __shared__ float sbuf[32];
    int i = threadIdx.x;
    float xv = g_x[i];
    float mu = block_sum(xv, sbuf) * (1.0f / Dm);
    float d  = xv - mu;
    float var = block_sum(d * d, sbuf) * (1.0f / Dm);
    g_xn[i] = d * rsqrtf(var + 1e-5f) * w[i] + b[i];
}

// logits = head @ xn. grid=6285x256, warp-per-row, guard row<V
__global__ void k_head(const float* __restrict__ head, float* __restrict__ logits) {
    __shared__ float sx[Dm];
    for (int j = threadIdx.x; j < Dm; j += 256) sx[j] = g_xn[j];
    __syncthreads();
    int warp = threadIdx.x >> 5, lane = threadIdx.x & 31;
    int row = (blockIdx.x << 3) + warp;
    if (row >= Vm) return;
    const float4* wr = (const float4*)(head + (size_t)row * Dm);
    const float4* xr4 = (const float4*)sx;
    float acc = 0.f;
#pragma unroll
    for (int j = 0; j < 8; j++) {
        float4 a = wr[j * 32 + lane];
        float4 c = xr4[j * 32 + lane];
        acc += a.x * c.x + a.y * c.y + a.z * c.z + a.w * c.w;
    }
    acc = warp_sum(acc);
    if (lane == 0) logits[row] = acc;
}

// ---------------- launch ----------------
extern "C" void kernel_launch(void* const* d_in, const int* in_sizes, int n_in,
                              void* d_out, int out_size) {
    const int*   tok    = (const int*)  d_in[0];
    const float* state  = (const float*)d_in[1];
    const float* emb    = (const float*)d_in[2];
    const float* ln0w   = (const float*)d_in[3];
    const float* ln0b   = (const float*)d_in[4];
    const float* ln1w   = (const float*)d_in[5];
    const float* ln1b   = (const float*)d_in[6];
    const float* tmk    = (const float*)d_in[7];
    const float* tmv    = (const float*)d_in[8];
    const float* tmr    = (const float*)d_in[9];
    const float* tf     = (const float*)d_in[10];
    const float* td     = (const float*)d_in[11];
    const float* kw     = (const float*)d_in[12];
    const float* vw     = (const float*)d_in[13];
    const float* rw     = (const float*)d_in[14];
    const float* ow     = (const float*)d_in[15];
    const float* ln2w   = (const float*)d_in[16];
    const float* ln2b   = (const float*)d_in[17];
    const float* fmk    = (const float*)d_in[18];
    const float* fmr    = (const float*)d_in[19];
    const float* fkw    = (const float*)d_in[20];
    const float* fvw    = (const float*)d_in[21];
    const float* frw    = (const float*)d_in[22];
    const float* lnoutw = (const float*)d_in[23];
    const float* lnoutb = (const float*)d_in[24];
    const float* headw  = (const float*)d_in[25];

    float* logits = (float*)d_out;
    float* ns     = (float*)d_out + Vm;   // new state [5L, D]

    k_embed<<<1, 1024>>>(tok, emb, ln0w, ln0b);

    for (int l = 0; l < Lm; l++) {
        const float* s   = state + (size_t)l * 5 * Dm;
        float*       nsl = ns    + (size_t)l * 5 * Dm;
        size_t dd = (size_t)l * Dm * Dm;
        size_t hd = (size_t)l * Hm * Dm;

        k_att_pre<<<1, 1024>>>(ln1w + l * Dm, ln1b + l * Dm,
                               tmk + l * Dm, tmv + l * Dm, tmr + l * Dm,
                               s + 1 * Dm, nsl + 1 * Dm);
        k_mv_kvr<<<384, 256>>>(kw + dd, vw + dd, rw + dd);
        k_wkv<<<1, 1024>>>(tf + l * Dm, td + l * Dm,
                           s + 2 * Dm, s + 3 * Dm, s + 4 * Dm,
                           nsl + 2 * Dm, nsl + 3 * Dm, nsl + 4 * Dm);
        k_mv_ow<<<128, 256>>>(ow + dd);
        k_ffn_pre<<<1, 1024>>>(ln2w + l * Dm, ln2b + l * Dm,
                               fmk + l * Dm, fmr + l * Dm,
                               s + 0 * Dm, nsl + 0 * Dm);
        k_mv_fkr<<<640, 256>>>(fkw + hd, frw + dd);
        k_mv_fv<<<128, 256>>>(fvw + hd);
    }

    k_final_ln<<<1, 1024>>>(lnoutw, lnoutb);
    k_head<<<(Vm + 7) / 8, 256>>>(headw, logits);
}

// round 2
// speedup vs baseline: 1.4116x; 1.4116x over previous
#include <cuda_runtime.h>
#include <math.h>

#define Dm 1024
#define Hm 4096
#define Lm 12
#define Vm 50277
#define NB 148
#define NT 1024
#define NWG (NB * 32)   // total warps in grid

// ---------------- global scratch (allocation-free) ----------------
__device__ float g_k[Dm], g_v[Dm], g_r[Dm];
__device__ float g_po[2 * Dm];        // ow partials [chunk][row]
__device__ float g_fk[Hm], g_fr[Dm];
__device__ float g_pf[4 * Dm];        // fv partials [chunk][row]

// ---------------- grid barrier (replay-safe, deterministic) ----------------
__device__ unsigned g_cnt3[3];
__device__ volatile unsigned g_gen;

__device__ __forceinline__ void gsync() {
    __syncthreads();
    if (threadIdx.x == 0) {
        __threadfence();
        unsigned g = g_gen;
        unsigned s = g % 3u;
        if (atomicAdd(&g_cnt3[s], 1u) == (unsigned)(gridDim.x - 1)) {
            g_cnt3[(g + 2u) % 3u] = 0u;   // reset slot for barrier g+2 (one full round of separation)
            __threadfence();
            g_gen = g + 1u;
        } else {
            while (g_gen == g) { }
        }
        __threadfence();
    }
    __syncthreads();
}

// ---------------- reductions ----------------
__device__ __forceinline__ float warp_sum(float v) {
#pragma unroll
    for (int o = 16; o; o >>= 1) v += __shfl_down_sync(0xffffffffu, v, o);
    return v;
}

__device__ __forceinline__ float block_sum(float v, float* sbuf) {
    int lane = threadIdx.x & 31, wid = threadIdx.x >> 5;
    v = warp_sum(v);
    __syncthreads();
    if (lane == 0) sbuf[wid] = v;
    __syncthreads();
    if (wid == 0) {
        float t = sbuf[lane];
        t = warp_sum(t);
        if (lane == 0) sbuf[0] = t;
    }
    __syncthreads();
    return sbuf[0];
}

// LN over the 1024-wide vector (thread i owns element i)
__device__ __forceinline__ float ln1024(float v, const float* __restrict__ w,
                                        const float* __restrict__ b, float* sbuf) {
    float mu = block_sum(v, sbuf) * (1.0f / Dm);
    float d = v - mu;
    float var = block_sum(d * d, sbuf) * (1.0f / Dm);
    return d * rsqrtf(var + 1e-5f) * w[threadIdx.x] + b[threadIdx.x];
}

// ---------------- dot helpers (warp-per-row, streaming weight loads) ----------------
__device__ __forceinline__ float dot8(const float4* __restrict__ w,
                                      const float4* __restrict__ x, int lane) {
    float acc = 0.f;
#pragma unroll
    for (int j = 0; j < 8; j++) {
        float4 a = __ldcs(w + j * 32 + lane);
        float4 c = x[j * 32 + lane];
        acc = fmaf(a.x, c.x, fmaf(a.y, c.y, fmaf(a.z, c.z, fmaf(a.w, c.w, acc))));
    }
    return warp_sum(acc);
}

__device__ __forceinline__ float dot4(const float4* __restrict__ w,
                                      const float4* __restrict__ x, int lane) {
    float acc = 0.f;
#pragma unroll
    for (int j = 0; j < 4; j++) {
        float4 a = __ldcs(w + j * 32 + lane);
        float4 c = x[j * 32 + lane];
        acc = fmaf(a.x, c.x, fmaf(a.y, c.y, fmaf(a.z, c.z, fmaf(a.w, c.w, acc))));
    }
    return warp_sum(acc);
}

// ---------------- the whole network in one persistent kernel ----------------
__global__ __launch_bounds__(NT, 1) void rwkv_all(
    const int* __restrict__ tok, const float* __restrict__ state,
    const float* __restrict__ emb,
    const float* __restrict__ ln0w, const float* __restrict__ ln0b,
    const float* __restrict__ ln1w, const float* __restrict__ ln1b,
    const float* __restrict__ tmk, const float* __restrict__ tmv,
    const float* __restrict__ tmr, const float* __restrict__ tf,
    const float* __restrict__ td,
    const float* __restrict__ kw, const float* __restrict__ vw,
    const float* __restrict__ rw, const float* __restrict__ ow,
    const float* __restrict__ ln2w, const float* __restrict__ ln2b,
    const float* __restrict__ fmk, const float* __restrict__ fmr,
    const float* __restrict__ fkw, const float* __restrict__ fvw,
    const float* __restrict__ frw,
    const float* __restrict__ lnoutw, const float* __restrict__ lnoutb,
    const float* __restrict__ headw,
    float* __restrict__ logits, float* __restrict__ ns)
{
    __shared__ float s_v0[Dm], s_v1[Dm], s_v2[Dm];
    __shared__ float s_fk[Hm];
    __shared__ float s_red[32];

    const int tid = threadIdx.x;
    const int wid = tid >> 5, lane = tid & 31;
    const int gw = blockIdx.x * 32 + wid;
    const bool b0 = (blockIdx.x == 0);

    // ---- embed + ln0 (redundant in every block; x lives in a register) ----
    float x = ln1024(emb[(size_t)(*tok) * Dm + tid], ln0w, ln0b, s_red);

    for (int l = 0; l < Lm; l++) {
        const float* s = state + (size_t)l * 5 * Dm;
        float* nsl = ns + (size_t)l * 5 * Dm;
        const size_t dd = (size_t)l * Dm * Dm;
        const size_t hd = (size_t)l * Hm * Dm;

        // ---- step 1: LN1 + token-mix, then k/v/r matvec ----
        {
            float xx = ln1024(x, ln1w + l * Dm, ln1b + l * Dm, s_red);
            float ss = s[1 * Dm + tid];
            float mk = tmk[l * Dm + tid], mv = tmv[l * Dm + tid], mr = tmr[l * Dm + tid];
            s_v0[tid] = xx * mk + ss * (1.0f - mk);
            s_v1[tid] = xx * mv + ss * (1.0f - mv);
            s_v2[tid] = xx * mr + ss * (1.0f - mr);
            if (b0) nsl[1 * Dm + tid] = xx;
        }
        __syncthreads();
        for (int t = gw; t < 3 * Dm; t += NWG) {
            int mat = t >> 10, row = t & (Dm - 1);
            const float* W = (mat == 0) ? (kw + dd) : (mat == 1) ? (vw + dd) : (rw + dd);
            const float* xv = (mat == 0) ? s_v0 : (mat == 1) ? s_v1 : s_v2;
            float acc = dot8((const float4*)(W + (size_t)row * Dm), (const float4*)xv, lane);
            if (lane == 0) {
                if (mat == 0)      g_k[row] = acc;
                else if (mat == 1) g_v[row] = acc;
                else               g_r[row] = 1.0f / (1.0f + expf(-acc));
            }
        }
        gsync();

        // ---- step 2: WKV recurrence (redundant) + ow matvec partials ----
        {
            float k = g_k[tid], v = g_v[tid];
            float aa = s[2 * Dm + tid], bb = s[3 * Dm + tid], pp = s[4 * Dm + tid];
            float ww = tf[l * Dm + tid] + k;
            float p = fmaxf(pp, ww);
            float e1 = expf(pp - p), e2 = expf(ww - p);
            float wkv = (e1 * aa + e2 * v) / (e1 * bb + e2);
            float ww2 = pp + td[l * Dm + tid];
            float p2 = fmaxf(ww2, k);
            float f1 = expf(ww2 - p2), f2 = expf(k - p2);
            s_v0[tid] = g_r[tid] * wkv;
            if (b0) {
                nsl[2 * Dm + tid] = f1 * aa + f2 * v;
                nsl[3 * Dm + tid] = f1 * bb + f2;
                nsl[4 * Dm + tid] = p2;
            }
        }
        __syncthreads();
        for (int t = gw; t < 2 * Dm; t += NWG) {       // 1024 rows x 2 K-chunks of 512
            int row = t >> 1, ch = t & 1;
            float acc = dot4((const float4*)(ow + dd + (size_t)row * Dm + ch * 512),
                             (const float4*)(s_v0 + ch * 512), lane);
            if (lane == 0) g_po[ch * Dm + row] = acc;
        }
        gsync();

        // ---- step 3: residual + LN2 + FFN mix, then fk/fr matvec ----
        x = x + g_po[tid] + g_po[Dm + tid];
        {
            float yy = ln1024(x, ln2w + l * Dm, ln2b + l * Dm, s_red);
            float sf = s[0 * Dm + tid];
            float mk = fmk[l * Dm + tid], mr = fmr[l * Dm + tid];
            s_v0[tid] = yy * mk + sf * (1.0f - mk);
            s_v1[tid] = yy * mr + sf * (1.0f - mr);
            if (b0) nsl[0 * Dm + tid] = yy;
        }
        __syncthreads();
        for (int t = gw; t < Hm + Dm; t += NWG) {      // 4096 fk rows + 1024 fr rows
            bool isk = (t < Hm);
            const float* W = isk ? (fkw + hd + (size_t)t * Dm)
                                 : (frw + dd + (size_t)(t - Hm) * Dm);
            float acc = dot8((const float4*)W, (const float4*)(isk ? s_v0 : s_v1), lane);
            if (lane == 0) {
                if (isk) { float u = fmaxf(acc, 0.0f); g_fk[t] = u * u; }
                else     { g_fr[t - Hm] = 1.0f / (1.0f + expf(-acc)); }
            }
        }
        gsync();

        // ---- step 4: fv matvec partials (K=4096 split into 4 chunks of 1024) ----
        for (int j = tid; j < Hm; j += NT) s_fk[j] = g_fk[j];
        __syncthreads();
        for (int t = gw; t < 4 * Dm; t += NWG) {
            int row = t >> 2, ch = t & 3;
            float acc = dot8((const float4*)(fvw + hd + (size_t)row * Hm + ch * Dm),
                             (const float4*)(s_fk + ch * Dm), lane);
            if (lane == 0) g_pf[ch * Dm + row] = acc;
        }
        gsync();

        // ---- residual update for next layer ----
        x = x + g_fr[tid] * (g_pf[tid] + g_pf[Dm + tid] + g_pf[2 * Dm + tid] + g_pf[3 * Dm + tid]);
    }

    // ---- final LN + head matvec ----
    {
        float xf = ln1024(x, lnoutw, lnoutb, s_red);
        s_v0[tid] = xf;
    }
    __syncthreads();
    for (int t = gw; t < Vm; t += NWG) {
        float acc = dot8((const float4*)(headw + (size_t)t * Dm), (const float4*)s_v0, lane);
        if (lane == 0) logits[t] = acc;
    }
}

// ---------------- launch ----------------
extern "C" void kernel_launch(void* const* d_in, const int* in_sizes, int n_in,
                              void* d_out, int out_size) {
    const int*   tok    = (const int*)  d_in[0];
    const float* state  = (const float*)d_in[1];
    const float* emb    = (const float*)d_in[2];
    const float* ln0w   = (const float*)d_in[3];
    const float* ln0b   = (const float*)d_in[4];
    const float* ln1w   = (const float*)d_in[5];
    const float* ln1b   = (const float*)d_in[6];
    const float* tmk    = (const float*)d_in[7];
    const float* tmv    = (const float*)d_in[8];
    const float* tmr    = (const float*)d_in[9];
    const float* tf     = (const float*)d_in[10];
    const float* td     = (const float*)d_in[11];
    const float* kw     = (const float*)d_in[12];
    const float* vw     = (const float*)d_in[13];
    const float* rw     = (const float*)d_in[14];
    const float* ow     = (const float*)d_in[15];
    const float* ln2w   = (const float*)d_in[16];
    const float* ln2b   = (const float*)d_in[17];
    const float* fmk    = (const float*)d_in[18];
    const float* fmr    = (const float*)d_in[19];
    const float* fkw    = (const float*)d_in[20];
    const float* fvw    = (const float*)d_in[21];
    const float* frw    = (const float*)d_in[22];
    const float* lnoutw = (const float*)d_in[23];
    const float* lnoutb = (const float*)d_in[24];
    const float* headw  = (const float*)d_in[25];

    float* logits = (float*)d_out;
    float* ns     = (float*)d_out + Vm;

    rwkv_all<<<NB, NT>>>(tok, state, emb, ln0w, ln0b, ln1w, ln1b,
                         tmk, tmv, tmr, tf, td, kw, vw, rw, ow,
                         ln2w, ln2b, fmk, fmr, fkw, fvw, frw,
                         lnoutw, lnoutb, headw, logits, ns);
}